// round 9
// baseline (speedup 1.0000x reference)
#include <cuda_runtime.h>
#include <cuda_fp16.h>
#include <cstdint>

#define N_NODES 100000
#define N_EDGES 1600000
#define HIDDEN  64
#define SCAN_B  1024
#define NBLK    ((N_NODES + SCAN_B - 1) / SCAN_B)   // 98

// ---------------- scratch (static device globals; no runtime alloc) -------
__device__ __align__(256) float  g_agg8[N_NODES * 8];      // [x0,x1,x2,ea0,ea1,ea2,deg,pad]
__device__ __align__(256) __half g_hh[N_NODES * HIDDEN];   // layer-1 output (fp16)
__device__ __align__(256) float  g_aggh[N_NODES * HIDDEN]; // layer-2 neighbor sum
__device__ __align__(256) int    g_src[N_EDGES];
__device__ __align__(256) int    g_dst[N_EDGES];
__device__ __align__(256) int    g_csr_src[N_EDGES];       // src ids grouped by dst
__device__ __align__(256) int    g_rowptr[N_NODES + 1];
__device__ __align__(256) int    g_fill[N_NODES];
__device__ __align__(256) int    g_blocksum[128];
__device__ __align__(256) int    g_blockoff[128];
__device__ int g_is64;

__device__ __forceinline__ void red_add_v4(float* addr, float a, float b, float c, float d) {
    asm volatile(
        "{ .reg .u64 p; cvta.to.global.u64 p, %0;\n"
        "  red.global.add.v4.f32 [p], {%1, %2, %3, %4}; }\n"
        :: "l"(addr), "f"(a), "f"(b), "f"(c), "f"(d) : "memory");
}

// ---------------- K0: detect edge_index dtype (parallel) -------------------
__global__ void k_detect(const int* __restrict__ ei32) {
    int lane = threadIdx.x;
    int nz = 0;
    if (ei32[4 * lane + 1] != 0) nz = 1;
    if (ei32[4 * lane + 3] != 0) nz = 1;
    unsigned m = __ballot_sync(0xffffffffu, nz);
    if (lane == 0) g_is64 = (m == 0) ? 1 : 0;
}

// ---------------- K1: zero agg8 --------------------------------------------
__global__ void k_zero() {
    int i = blockIdx.x * blockDim.x + threadIdx.x;
    int stride = gridDim.x * blockDim.x;
    float4 z = make_float4(0.f, 0.f, 0.f, 0.f);
    for (int t = i; t < (N_NODES * 8) / 4; t += stride)
        reinterpret_cast<float4*>(g_agg8)[t] = z;
}

// ---------------- K2: edge pass 1, 2 edges per thread ----------------------
__global__ void k_edge1(const float* __restrict__ x,
                        const void* __restrict__ ei,
                        const float* __restrict__ ea) {
    int t = blockIdx.x * blockDim.x + threadIdx.x;
    int e = 2 * t;
    if (e >= N_EDGES) return;
    int s0, s1, d0, d1;
    if (g_is64) {
        const longlong2* ps = (const longlong2*)ei;
        longlong2 sp = ps[t];
        longlong2 dp = ps[(N_EDGES / 2) + t];
        s0 = (int)sp.x; s1 = (int)sp.y;
        d0 = (int)dp.x; d1 = (int)dp.y;
    } else {
        const int2* ps = (const int2*)ei;
        int2 sp = ps[t];
        int2 dp = ps[(N_EDGES / 2) + t];
        s0 = sp.x; s1 = sp.y;
        d0 = dp.x; d1 = dp.y;
    }
    reinterpret_cast<int2*>(g_src)[t] = make_int2(s0, s1);
    reinterpret_cast<int2*>(g_dst)[t] = make_int2(d0, d1);

    const float2* pea = (const float2*)(ea + 6 * (size_t)t);
    float2 a01 = pea[0];
    float2 a23 = pea[1];
    float2 a45 = pea[2];

    float x00 = __ldg(&x[s0 * 3 + 0]);
    float x01 = __ldg(&x[s0 * 3 + 1]);
    float x02 = __ldg(&x[s0 * 3 + 2]);
    float x10 = __ldg(&x[s1 * 3 + 0]);
    float x11 = __ldg(&x[s1 * 3 + 1]);
    float x12 = __ldg(&x[s1 * 3 + 2]);

    float* b0 = &g_agg8[(size_t)d0 * 8];
    red_add_v4(b0,     x00, x01, x02, a01.x);
    red_add_v4(b0 + 4, a01.y, a23.x, 1.0f, 0.0f);
    float* b1p = &g_agg8[(size_t)d1 * 8];
    red_add_v4(b1p,     x10, x11, x12, a23.y);
    red_add_v4(b1p + 4, a45.x, a45.y, 1.0f, 0.0f);
}

// ---------------- K3a: per-block scan of degrees ---------------------------
__global__ void k_scan_blk() {
    __shared__ int sh[SCAN_B];
    int t = threadIdx.x;
    int i = blockIdx.x * SCAN_B + t;
    int d = (i < N_NODES) ? (int)g_agg8[(size_t)i * 8 + 6] : 0;
    sh[t] = d;
    __syncthreads();
    #pragma unroll
    for (int off = 1; off < SCAN_B; off <<= 1) {
        int v = (t >= off) ? sh[t - off] : 0;
        __syncthreads();
        sh[t] += v;
        __syncthreads();
    }
    if (i < N_NODES) g_rowptr[i] = sh[t] - d;
    if (t == SCAN_B - 1) g_blocksum[blockIdx.x] = sh[t];
}

// ---------------- K3b: scan of the block sums ------------------------------
__global__ void k_scan_top() {
    __shared__ int sh[128];
    int t = threadIdx.x;
    int v = (t < NBLK) ? g_blocksum[t] : 0;
    sh[t] = v;
    __syncthreads();
    #pragma unroll
    for (int off = 1; off < 128; off <<= 1) {
        int u = (t >= off) ? sh[t - off] : 0;
        __syncthreads();
        sh[t] += u;
        __syncthreads();
    }
    if (t < NBLK) g_blockoff[t] = sh[t] - v;
    if (t == 127) g_rowptr[N_NODES] = sh[127];
}

// ---------------- K3c: add block offsets; init fill cursors ----------------
__global__ void k_scan_add() {
    int i = blockIdx.x * blockDim.x + threadIdx.x;
    if (i >= N_NODES) return;
    int r = g_rowptr[i] + g_blockoff[i >> 10];
    g_rowptr[i] = r;
    g_fill[i]   = r;
}

// ---------------- K4: scatter src ids into dst-grouped CSR -----------------
__global__ void k_scatter() {
    int e = blockIdx.x * blockDim.x + threadIdx.x;
    if (e >= N_EDGES) return;
    int d = g_dst[e];
    int pos = atomicAdd(&g_fill[d], 1);
    g_csr_src[pos] = g_src[e];
}

// ---------------- K5: node pass 1 (6->64 linear + ReLU) -> fp16 ------------
__global__ void k_node1(const float* __restrict__ W1, const float* __restrict__ b1) {
    __shared__ float sa[16 * 8];
    int tid = threadIdx.x;
    int base = blockIdx.x * 16;
    if (tid < 32)
        reinterpret_cast<float4*>(sa)[tid] =
            reinterpret_cast<const float4*>(&g_agg8[(size_t)base * 8])[tid];
    __syncthreads();
    int nl = tid >> 4;
    int quad = tid & 15;
    const float* a = &sa[nl * 8];
    float deg = a[6];
    float oc[4];
    #pragma unroll
    for (int c = 0; c < 4; c++) {
        int j = quad * 4 + c;
        float acc = deg * __ldg(&b1[j]);
        #pragma unroll
        for (int k = 0; k < 6; k++)
            acc += a[k] * __ldg(&W1[k * 64 + j]);
        oc[c] = fmaxf(acc, 0.0f);
    }
    __half2 h0 = __floats2half2_rn(oc[0], oc[1]);
    __half2 h1 = __floats2half2_rn(oc[2], oc[3]);
    uint2 packed;
    packed.x = *reinterpret_cast<unsigned*>(&h0);
    packed.y = *reinterpret_cast<unsigned*>(&h1);
    *reinterpret_cast<uint2*>(&g_hh[(size_t)(base + nl) * 64 + quad * 4]) = packed;
}

// ---------------- K6: layer-2 CSR gather, 4 edges/iter, high MLP -----------
__global__ void k_agg2() {
    int warp = (blockIdx.x * blockDim.x + threadIdx.x) >> 5;
    if (warp >= N_NODES) return;
    int lane = threadIdx.x & 31;
    int grp = lane >> 3;
    int oct = lane & 7;
    int start = __ldg(&g_rowptr[warp]);
    int deg   = __ldg(&g_rowptr[warp + 1]) - start;
    float acc[8];
    #pragma unroll
    for (int c = 0; c < 8; c++) acc[c] = 0.0f;

    #pragma unroll 4
    for (int i = grp; i < deg; i += 4) {
        int s = __ldg(&g_csr_src[start + i]);
        uint4 raw = *reinterpret_cast<const uint4*>(&g_hh[(size_t)s * 64 + oct * 8]);
        float2 f0 = __half22float2(*reinterpret_cast<__half2*>(&raw.x));
        float2 f1 = __half22float2(*reinterpret_cast<__half2*>(&raw.y));
        float2 f2 = __half22float2(*reinterpret_cast<__half2*>(&raw.z));
        float2 f3 = __half22float2(*reinterpret_cast<__half2*>(&raw.w));
        acc[0] += f0.x; acc[1] += f0.y; acc[2] += f1.x; acc[3] += f1.y;
        acc[4] += f2.x; acc[5] += f2.y; acc[6] += f3.x; acc[7] += f3.y;
    }
    #pragma unroll
    for (int c = 0; c < 8; c++) {
        acc[c] += __shfl_xor_sync(0xffffffffu, acc[c], 8);
        acc[c] += __shfl_xor_sync(0xffffffffu, acc[c], 16);
    }
    if (grp == 0) {
        float* dst = &g_aggh[(size_t)warp * 64 + oct * 8];
        *reinterpret_cast<float4*>(dst)     = make_float4(acc[0], acc[1], acc[2], acc[3]);
        *reinterpret_cast<float4*>(dst + 4) = make_float4(acc[4], acc[5], acc[6], acc[7]);
    }
}

// ---------------- K7: node pass 2 — register-tiled smem GEMM + head --------
// block = 256 threads, 64 nodes. thread = (q = j-quad 0..15, g = group 0..15),
// computes 4 nodes x 4 j. Zero LDG in the hot loop: W2/b2 and node rows smem-
// staged. i runs 0..67: [aggh(64) | ea_agg(3) | deg], W2 rows 0..66 + b2.
#define ASTRIDE 68
#define N2_NODES 64
__global__ void k_node2(const float* __restrict__ W2, const float* __restrict__ b2,
                        const float* __restrict__ W3, const float* __restrict__ b3,
                        float* __restrict__ out) {
    __shared__ float sW[68 * 64];             // rows 0..66: W2, row 67: b2
    __shared__ float sA[N2_NODES * ASTRIDE];  // per node: aggh[64], ea0..2, deg
    int tid = threadIdx.x;
    int nb = blockIdx.x * N2_NODES;

    // stage W2 (67*64 = 4288 floats = 1072 float4)
    for (int v = tid; v < 1072; v += 256)
        reinterpret_cast<float4*>(sW)[v] = __ldg(&reinterpret_cast<const float4*>(W2)[v]);
    // stage b2 as row 67 (64 floats = 16 float4)
    if (tid < 16)
        reinterpret_cast<float4*>(sW)[1072 + tid] = __ldg(&reinterpret_cast<const float4*>(b2)[tid]);
    // stage aggh rows (64 nodes x 16 float4)
    for (int v = tid; v < N2_NODES * 16; v += 256) {
        int n = v >> 4, k = v & 15;
        float4 val = make_float4(0.f, 0.f, 0.f, 0.f);
        if (nb + n < N_NODES)
            val = reinterpret_cast<const float4*>(g_aggh)[(size_t)(nb + n) * 16 + k];
        *reinterpret_cast<float4*>(&sA[n * ASTRIDE + k * 4]) = val;
    }
    // stage ea_agg + deg
    for (int v = tid; v < N2_NODES; v += 256) {
        float e0 = 0.f, e1 = 0.f, e2 = 0.f, dg = 0.f;
        if (nb + v < N_NODES) {
            const float* a8 = &g_agg8[(size_t)(nb + v) * 8];
            e0 = a8[3]; e1 = a8[4]; e2 = a8[5]; dg = a8[6];
        }
        sA[v * ASTRIDE + 64] = e0;
        sA[v * ASTRIDE + 65] = e1;
        sA[v * ASTRIDE + 66] = e2;
        sA[v * ASTRIDE + 67] = dg;
    }
    __syncthreads();

    int q = tid & 15;
    int g = tid >> 4;
    const float* a0 = &sA[(g * 4 + 0) * ASTRIDE];
    const float* a1 = &sA[(g * 4 + 1) * ASTRIDE];
    const float* a2 = &sA[(g * 4 + 2) * ASTRIDE];
    const float* a3 = &sA[(g * 4 + 3) * ASTRIDE];

    float acc0x = 0.f, acc0y = 0.f, acc0z = 0.f, acc0w = 0.f;
    float acc1x = 0.f, acc1y = 0.f, acc1z = 0.f, acc1w = 0.f;
    float acc2x = 0.f, acc2y = 0.f, acc2z = 0.f, acc2w = 0.f;
    float acc3x = 0.f, acc3y = 0.f, acc3z = 0.f, acc3w = 0.f;

    #pragma unroll 4
    for (int i = 0; i < 68; i++) {
        float4 w = *reinterpret_cast<const float4*>(&sW[i * 64 + q * 4]);
        float v0 = a0[i], v1 = a1[i], v2 = a2[i], v3 = a3[i];
        acc0x += v0 * w.x; acc0y += v0 * w.y; acc0z += v0 * w.z; acc0w += v0 * w.w;
        acc1x += v1 * w.x; acc1y += v1 * w.y; acc1z += v1 * w.z; acc1w += v1 * w.w;
        acc2x += v2 * w.x; acc2y += v2 * w.y; acc2z += v2 * w.z; acc2w += v2 * w.w;
        acc3x += v3 * w.x; acc3y += v3 * w.y; acc3z += v3 * w.z; acc3w += v3 * w.w;
    }

    // head: out[n] = sum_j relu(h2)*W3[j] + b3, reduced over 16 q-lanes
    float w3x = __ldg(&W3[q * 4 + 0]);
    float w3y = __ldg(&W3[q * 4 + 1]);
    float w3z = __ldg(&W3[q * 4 + 2]);
    float w3w = __ldg(&W3[q * 4 + 3]);
    float b3v = __ldg(&b3[0]);

    #pragma unroll
    for (int n = 0; n < 4; n++) {
        float vx, vy, vz, vw;
        if (n == 0)      { vx = acc0x; vy = acc0y; vz = acc0z; vw = acc0w; }
        else if (n == 1) { vx = acc1x; vy = acc1y; vz = acc1z; vw = acc1w; }
        else if (n == 2) { vx = acc2x; vy = acc2y; vz = acc2z; vw = acc2w; }
        else             { vx = acc3x; vy = acc3y; vz = acc3z; vw = acc3w; }
        float val = fmaxf(vx, 0.f) * w3x + fmaxf(vy, 0.f) * w3y
                  + fmaxf(vz, 0.f) * w3z + fmaxf(vw, 0.f) * w3w;
        val += __shfl_xor_sync(0xffffffffu, val, 1);
        val += __shfl_xor_sync(0xffffffffu, val, 2);
        val += __shfl_xor_sync(0xffffffffu, val, 4);
        val += __shfl_xor_sync(0xffffffffu, val, 8);
        int node = nb + g * 4 + n;
        if (q == 0 && node < N_NODES)
            out[node] = val + b3v;
    }
}

// ---------------- launch ---------------------------------------------------
extern "C" void kernel_launch(void* const* d_in, const int* in_sizes, int n_in,
                              void* d_out, int out_size) {
    const float* x   = (const float*)d_in[0];
    const void*  ei  = d_in[1];
    const float* ea  = (const float*)d_in[2];
    const float* W1  = (const float*)d_in[3];
    const float* b1  = (const float*)d_in[4];
    const float* W2  = (const float*)d_in[5];
    const float* b2  = (const float*)d_in[6];
    const float* W3  = (const float*)d_in[7];
    const float* b3  = (const float*)d_in[8];
    float* out = (float*)d_out;

    k_detect<<<1, 32>>>((const int*)ei);
    k_zero<<<800, 256>>>();
    k_edge1<<<(N_EDGES / 2 + 255) / 256, 256>>>(x, ei, ea);
    k_scan_blk<<<NBLK, SCAN_B>>>();
    k_scan_top<<<1, 128>>>();
    k_scan_add<<<(N_NODES + 255) / 256, 256>>>();
    k_scatter<<<(N_EDGES + 255) / 256, 256>>>();
    k_node1<<<N_NODES / 16, 256>>>(W1, b1);
    k_agg2<<<(N_NODES * 32 + 255) / 256, 256>>>();
    k_node2<<<(N_NODES + N2_NODES - 1) / N2_NODES, 256>>>(W2, b2, W3, b3, out);
}